// round 16
// baseline (speedup 1.0000x reference)
#include <cuda_runtime.h>
#include <cuda_bf16.h>
#include <cstdint>

#define N_NODES 50000
#define MAXE    1600000
#define MAXF    256
#define NB_SCAN ((N_NODES + 255) / 256)   // 196

// Static scratch (allocation-free rule).
__device__ float g_p[(size_t)N_NODES * MAXF];     // dinv-scaled transformed features
__device__ float g_act[(size_t)N_NODES * MAXF];   // layer activations
__device__ float g_dinv[N_NODES];
__device__ int   g_ideg[N_NODES];
__device__ int   g_cursor[N_NODES];
__device__ int   g_rowptr[N_NODES + 1];
__device__ int   g_csr_src[MAXE];
__device__ int   g_partial[NB_SCAN];

// ---------------- prep kernels ----------------

__global__ void init_counts_kernel(int* ideg, int* cursor) {
    int i = blockIdx.x * blockDim.x + threadIdx.x;
    if (i < N_NODES) { ideg[i] = 0; cursor[i] = 0; }
}

// edge_index is int32 on device (JAX x64 disabled).
__global__ void edge_count_kernel(const int* __restrict__ ei, int* __restrict__ ideg, int E) {
    int e = blockIdx.x * blockDim.x + threadIdx.x;
    if (e >= E) return;
    int d = ei[E + e];
    if ((unsigned)d >= N_NODES) d = 0;
    atomicAdd(&ideg[d], 1);
}

__global__ void dinv_kernel(const int* __restrict__ ideg, float* __restrict__ dinv) {
    int i = blockIdx.x * blockDim.x + threadIdx.x;
    if (i < N_NODES) dinv[i] = rsqrtf(1.0f + (float)ideg[i]);
}

// --- 3-phase parallel exclusive scan: ideg -> rowptr ---

__global__ void scan_reduce_kernel(const int* __restrict__ ideg, int* __restrict__ partial) {
    __shared__ int s[256];
    int tid = threadIdx.x;
    int idx = blockIdx.x * 256 + tid;
    s[tid] = (idx < N_NODES) ? ideg[idx] : 0;
    __syncthreads();
#pragma unroll
    for (int off = 128; off > 0; off >>= 1) {
        if (tid < off) s[tid] += s[tid + off];
        __syncthreads();
    }
    if (tid == 0) partial[blockIdx.x] = s[0];
}

__global__ void scan_partials_kernel(int* __restrict__ partial) {
    __shared__ int s[256];
    int tid = threadIdx.x;
    int v = (tid < NB_SCAN) ? partial[tid] : 0;
    s[tid] = v;
    __syncthreads();
#pragma unroll
    for (int off = 1; off < 256; off <<= 1) {
        int t = (tid >= off) ? s[tid - off] : 0;
        __syncthreads();
        s[tid] += t;
        __syncthreads();
    }
    if (tid < NB_SCAN) partial[tid] = s[tid] - v;  // exclusive
}

__global__ void scan_final_kernel(const int* __restrict__ ideg, const int* __restrict__ partial,
                                  int* __restrict__ rowptr) {
    __shared__ int s[256];
    int tid = threadIdx.x;
    int idx = blockIdx.x * 256 + tid;
    int v = (idx < N_NODES) ? ideg[idx] : 0;
    s[tid] = v;
    __syncthreads();
#pragma unroll
    for (int off = 1; off < 256; off <<= 1) {
        int t = (tid >= off) ? s[tid - off] : 0;
        __syncthreads();
        s[tid] += t;
        __syncthreads();
    }
    if (idx < N_NODES) rowptr[idx + 1] = partial[blockIdx.x] + s[tid];
    if (idx == 0) rowptr[0] = 0;
}

__global__ void edge_fill_kernel(const int* __restrict__ ei, const int* __restrict__ rowptr,
                                 int* __restrict__ cursor, int* __restrict__ csr_src, int E) {
    int e = blockIdx.x * blockDim.x + threadIdx.x;
    if (e >= E) return;
    int s = ei[e];
    int d = ei[E + e];
    if ((unsigned)s >= N_NODES) s = 0;
    if ((unsigned)d >= N_NODES) d = 0;
    int pos = rowptr[d] + atomicAdd(&cursor[d], 1);
    csr_src[pos] = s;
}

// ---------------- GEMM: C[N,M] = dinv[row] * (A[N,K] @ B[K,M]) ----------------
// 128-wide block tiles, 8xTN micro-tiles, float4 global loads.

template <int BM, int BN, int BK, int TM, int TN>
__global__ void gemm_scaled_kernel(const float* __restrict__ A, const float* __restrict__ B,
                                   const float* __restrict__ dinv, float* __restrict__ C,
                                   int N, int K, int M) {
    constexpr int THREADS = (BM / TM) * (BN / TN);
    constexpr int KV = BK / 4;           // float4 groups along k in A tile
    __shared__ float As[BK][BM];
    __shared__ float Bs[BK][BN];

    const int tid = threadIdx.x;
    const int tx = tid % (BN / TN);
    const int ty = tid / (BN / TN);
    const int rowBase = blockIdx.y * BM;
    const int colBase = blockIdx.x * BN;

    float acc[TM][TN];
#pragma unroll
    for (int i = 0; i < TM; i++)
#pragma unroll
        for (int j = 0; j < TN; j++) acc[i][j] = 0.0f;

    for (int k0 = 0; k0 < K; k0 += BK) {
        // A tile: BM x BK, float4 along k, store transposed As[k][m]
#pragma unroll
        for (int v = tid; v < BM * KV; v += THREADS) {
            int m = v / KV;
            int q = v % KV;
            int r = rowBase + m;
            float4 a4 = make_float4(0.f, 0.f, 0.f, 0.f);
            if (r < N) a4 = *reinterpret_cast<const float4*>(A + (size_t)r * K + k0 + q * 4);
            As[q * 4 + 0][m] = a4.x;
            As[q * 4 + 1][m] = a4.y;
            As[q * 4 + 2][m] = a4.z;
            As[q * 4 + 3][m] = a4.w;
        }
        // B tile: BK x BN, float4 along n
#pragma unroll
        for (int v = tid; v < BK * (BN / 4); v += THREADS) {
            int k = v / (BN / 4);
            int q = v % (BN / 4);
            float4 b4 = *reinterpret_cast<const float4*>(B + (size_t)(k0 + k) * M + colBase + q * 4);
            *reinterpret_cast<float4*>(&Bs[k][q * 4]) = b4;
        }
        __syncthreads();

#pragma unroll
        for (int k = 0; k < BK; k++) {
            float aR[TM], bR[TN];
#pragma unroll
            for (int i = 0; i < TM; i++) aR[i] = As[k][ty * TM + i];
#pragma unroll
            for (int j = 0; j < TN; j++) bR[j] = Bs[k][tx * TN + j];
#pragma unroll
            for (int i = 0; i < TM; i++)
#pragma unroll
                for (int j = 0; j < TN; j++) acc[i][j] += aR[i] * bR[j];
        }
        __syncthreads();
    }

#pragma unroll
    for (int i = 0; i < TM; i++) {
        int r = rowBase + ty * TM + i;
        if (r >= N) continue;
        float dv = dinv[r];
#pragma unroll
        for (int j = 0; j < TN; j++) {
            C[(size_t)r * M + colBase + tx * TN + j] = acc[i][j] * dv;
        }
    }
}

// ---------------- propagate: out[i] = relu(dinv[i]*(p[i] + sum_in p[src]) + b) ----------------

template <int M>
__global__ void propagate_kernel(const float* __restrict__ p, const int* __restrict__ rowptr,
                                 const int* __restrict__ csr_src, const float* __restrict__ dinv,
                                 const float* __restrict__ bias, float* __restrict__ out) {
    constexpr int NPB = 256 / M;
    int node = blockIdx.x * NPB + threadIdx.y;
    if (node >= N_NODES) return;
    int f = threadIdx.x;

    float acc = p[(size_t)node * M + f];  // self-loop contribution (pre-dinv)
    int e = rowptr[node];
    int end = rowptr[node + 1];

    for (; e + 4 <= end; e += 4) {
        int s0 = csr_src[e + 0];
        int s1 = csr_src[e + 1];
        int s2 = csr_src[e + 2];
        int s3 = csr_src[e + 3];
        float v0 = p[(size_t)s0 * M + f];
        float v1 = p[(size_t)s1 * M + f];
        float v2 = p[(size_t)s2 * M + f];
        float v3 = p[(size_t)s3 * M + f];
        acc += (v0 + v1) + (v2 + v3);
    }
    for (; e < end; e++) acc += p[(size_t)csr_src[e] * M + f];

    out[(size_t)node * M + f] = fmaxf(fmaf(dinv[node], acc, bias[f]), 0.0f);
}

// ---------------- host-side drivers ----------------

static void run_gemm(const float* A, const float* B, const float* dinv, float* C,
                     int N, int K, int M) {
    if (M >= 128) {
        constexpr int BM = 128, BN = 128, BK = 16, TM = 8, TN = 8;
        dim3 grid(M / BN, (N + BM - 1) / BM);
        gemm_scaled_kernel<BM, BN, BK, TM, TN><<<grid, (BM / TM) * (BN / TN)>>>(A, B, dinv, C, N, K, M);
    } else if (M == 64) {
        constexpr int BM = 128, BN = 64, BK = 16, TM = 8, TN = 4;
        dim3 grid(M / BN, (N + BM - 1) / BM);
        gemm_scaled_kernel<BM, BN, BK, TM, TN><<<grid, (BM / TM) * (BN / TN)>>>(A, B, dinv, C, N, K, M);
    } else {  // M == 32
        constexpr int BM = 256, BN = 32, BK = 16, TM = 8, TN = 4;
        dim3 grid(M / BN, (N + BM - 1) / BM);
        gemm_scaled_kernel<BM, BN, BK, TM, TN><<<grid, (BM / TM) * (BN / TN)>>>(A, B, dinv, C, N, K, M);
    }
}

template <int M>
static void run_propagate(const float* p, const int* rowptr, const int* csr_src,
                          const float* dinv, const float* bias, float* out) {
    constexpr int NPB = 256 / M;
    dim3 block(M, NPB);
    dim3 grid((N_NODES + NPB - 1) / NPB);
    propagate_kernel<M><<<grid, block>>>(p, rowptr, csr_src, dinv, bias, out);
}

extern "C" void kernel_launch(void* const* d_in, const int* in_sizes, int n_in,
                              void* d_out, int out_size) {
    const float* x  = (const float*)d_in[0];
    const int*   ei = (const int*)d_in[1];
    const float* W1 = (const float*)d_in[2];
    const float* b1 = (const float*)d_in[3];
    const float* W2 = (const float*)d_in[4];
    const float* b2 = (const float*)d_in[5];
    const float* W3 = (const float*)d_in[6];
    const float* b3 = (const float*)d_in[7];
    const float* W4 = (const float*)d_in[8];
    const float* b4 = (const float*)d_in[9];

    const int E = in_sizes[1] / 2;

    float *p, *act, *dinv;
    int *ideg, *cursor, *rowptr, *csr_src, *partial;
    cudaGetSymbolAddress((void**)&p, g_p);
    cudaGetSymbolAddress((void**)&act, g_act);
    cudaGetSymbolAddress((void**)&dinv, g_dinv);
    cudaGetSymbolAddress((void**)&ideg, g_ideg);
    cudaGetSymbolAddress((void**)&cursor, g_cursor);
    cudaGetSymbolAddress((void**)&rowptr, g_rowptr);
    cudaGetSymbolAddress((void**)&csr_src, g_csr_src);
    cudaGetSymbolAddress((void**)&partial, g_partial);

    // --- prep: degree histogram, dinv, parallel scan, CSR fill ---
    init_counts_kernel<<<(N_NODES + 255) / 256, 256>>>(ideg, cursor);
    edge_count_kernel<<<(E + 255) / 256, 256>>>(ei, ideg, E);
    dinv_kernel<<<(N_NODES + 255) / 256, 256>>>(ideg, dinv);
    scan_reduce_kernel<<<NB_SCAN, 256>>>(ideg, partial);
    scan_partials_kernel<<<1, 256>>>(partial);
    scan_final_kernel<<<NB_SCAN, 256>>>(ideg, partial, rowptr);
    edge_fill_kernel<<<(E + 255) / 256, 256>>>(ei, rowptr, cursor, csr_src, E);

    // --- 4 GCN layers: p = dinv*(act@W); out = relu(dinv*(p_self + gather) + b) ---
    run_gemm(x,   W1, dinv, p, N_NODES, 128, 256);
    run_propagate<256>(p, rowptr, csr_src, dinv, b1, act);

    run_gemm(act, W2, dinv, p, N_NODES, 256, 128);
    run_propagate<128>(p, rowptr, csr_src, dinv, b2, act);

    run_gemm(act, W3, dinv, p, N_NODES, 128, 64);
    run_propagate<64>(p, rowptr, csr_src, dinv, b3, act);

    run_gemm(act, W4, dinv, p, N_NODES, 64, 32);
    run_propagate<32>(p, rowptr, csr_src, dinv, b4, (float*)d_out);
}

// round 17
// speedup vs baseline: 1.0026x; 1.0026x over previous
#include <cuda_runtime.h>
#include <cuda_bf16.h>
#include <cstdint>

#define N_NODES 50000
#define MAXE    1600000
#define MAXF    256
#define NB_SCAN ((N_NODES + 255) / 256)   // 196

// Static scratch (allocation-free rule).
__device__ float g_p[(size_t)N_NODES * MAXF];     // dinv-scaled transformed features
__device__ float g_act[(size_t)N_NODES * MAXF];   // layer activations
__device__ float g_dinv[N_NODES];
__device__ int   g_ideg[N_NODES];
__device__ int   g_cursor[N_NODES];
__device__ int   g_rowptr[N_NODES + 1];
__device__ int   g_csr_src[MAXE];
__device__ int   g_partial[NB_SCAN];

// ---------------- prep kernels ----------------

__global__ void init_counts_kernel(int* ideg, int* cursor) {
    int i = blockIdx.x * blockDim.x + threadIdx.x;
    if (i < N_NODES) { ideg[i] = 0; cursor[i] = 0; }
}

// edge_index is int32 on device (JAX x64 disabled).
__global__ void edge_count_kernel(const int* __restrict__ ei, int* __restrict__ ideg, int E) {
    int e = blockIdx.x * blockDim.x + threadIdx.x;
    if (e >= E) return;
    int d = ei[E + e];
    if ((unsigned)d >= N_NODES) d = 0;
    atomicAdd(&ideg[d], 1);
}

__global__ void dinv_kernel(const int* __restrict__ ideg, float* __restrict__ dinv) {
    int i = blockIdx.x * blockDim.x + threadIdx.x;
    if (i < N_NODES) dinv[i] = rsqrtf(1.0f + (float)ideg[i]);
}

// --- 3-phase parallel exclusive scan: ideg -> rowptr ---

__global__ void scan_reduce_kernel(const int* __restrict__ ideg, int* __restrict__ partial) {
    __shared__ int s[256];
    int tid = threadIdx.x;
    int idx = blockIdx.x * 256 + tid;
    s[tid] = (idx < N_NODES) ? ideg[idx] : 0;
    __syncthreads();
#pragma unroll
    for (int off = 128; off > 0; off >>= 1) {
        if (tid < off) s[tid] += s[tid + off];
        __syncthreads();
    }
    if (tid == 0) partial[blockIdx.x] = s[0];
}

__global__ void scan_partials_kernel(int* __restrict__ partial) {
    __shared__ int s[256];
    int tid = threadIdx.x;
    int v = (tid < NB_SCAN) ? partial[tid] : 0;
    s[tid] = v;
    __syncthreads();
#pragma unroll
    for (int off = 1; off < 256; off <<= 1) {
        int t = (tid >= off) ? s[tid - off] : 0;
        __syncthreads();
        s[tid] += t;
        __syncthreads();
    }
    if (tid < NB_SCAN) partial[tid] = s[tid] - v;  // exclusive
}

__global__ void scan_final_kernel(const int* __restrict__ ideg, const int* __restrict__ partial,
                                  int* __restrict__ rowptr) {
    __shared__ int s[256];
    int tid = threadIdx.x;
    int idx = blockIdx.x * 256 + tid;
    int v = (idx < N_NODES) ? ideg[idx] : 0;
    s[tid] = v;
    __syncthreads();
#pragma unroll
    for (int off = 1; off < 256; off <<= 1) {
        int t = (tid >= off) ? s[tid - off] : 0;
        __syncthreads();
        s[tid] += t;
        __syncthreads();
    }
    if (idx < N_NODES) rowptr[idx + 1] = partial[blockIdx.x] + s[tid];
    if (idx == 0) rowptr[0] = 0;
}

__global__ void edge_fill_kernel(const int* __restrict__ ei, const int* __restrict__ rowptr,
                                 int* __restrict__ cursor, int* __restrict__ csr_src, int E) {
    int e = blockIdx.x * blockDim.x + threadIdx.x;
    if (e >= E) return;
    int s = ei[e];
    int d = ei[E + e];
    if ((unsigned)s >= N_NODES) s = 0;
    if ((unsigned)d >= N_NODES) d = 0;
    int pos = rowptr[d] + atomicAdd(&cursor[d], 1);
    csr_src[pos] = s;
}

// ---------------- GEMM: C[N,M] = dinv[row] * (A[N,K] @ B[K,M]) ----------------
// 128-wide block tiles, 8xTN micro-tiles, float4 global loads.

template <int BM, int BN, int BK, int TM, int TN>
__global__ void gemm_scaled_kernel(const float* __restrict__ A, const float* __restrict__ B,
                                   const float* __restrict__ dinv, float* __restrict__ C,
                                   int N, int K, int M) {
    constexpr int THREADS = (BM / TM) * (BN / TN);
    constexpr int KV = BK / 4;           // float4 groups along k in A tile
    __shared__ float As[BK][BM];
    __shared__ float Bs[BK][BN];

    const int tid = threadIdx.x;
    const int tx = tid % (BN / TN);
    const int ty = tid / (BN / TN);
    const int rowBase = blockIdx.y * BM;
    const int colBase = blockIdx.x * BN;

    float acc[TM][TN];
#pragma unroll
    for (int i = 0; i < TM; i++)
#pragma unroll
        for (int j = 0; j < TN; j++) acc[i][j] = 0.0f;

    for (int k0 = 0; k0 < K; k0 += BK) {
        // A tile: BM x BK, float4 along k, store transposed As[k][m]
#pragma unroll
        for (int v = tid; v < BM * KV; v += THREADS) {
            int m = v / KV;
            int q = v % KV;
            int r = rowBase + m;
            float4 a4 = make_float4(0.f, 0.f, 0.f, 0.f);
            if (r < N) a4 = *reinterpret_cast<const float4*>(A + (size_t)r * K + k0 + q * 4);
            As[q * 4 + 0][m] = a4.x;
            As[q * 4 + 1][m] = a4.y;
            As[q * 4 + 2][m] = a4.z;
            As[q * 4 + 3][m] = a4.w;
        }
        // B tile: BK x BN, float4 along n
#pragma unroll
        for (int v = tid; v < BK * (BN / 4); v += THREADS) {
            int k = v / (BN / 4);
            int q = v % (BN / 4);
            float4 b4 = *reinterpret_cast<const float4*>(B + (size_t)(k0 + k) * M + colBase + q * 4);
            *reinterpret_cast<float4*>(&Bs[k][q * 4]) = b4;
        }
        __syncthreads();

#pragma unroll
        for (int k = 0; k < BK; k++) {
            float aR[TM], bR[TN];
#pragma unroll
            for (int i = 0; i < TM; i++) aR[i] = As[k][ty * TM + i];
#pragma unroll
            for (int j = 0; j < TN; j++) bR[j] = Bs[k][tx * TN + j];
#pragma unroll
            for (int i = 0; i < TM; i++)
#pragma unroll
                for (int j = 0; j < TN; j++) acc[i][j] += aR[i] * bR[j];
        }
        __syncthreads();
    }

#pragma unroll
    for (int i = 0; i < TM; i++) {
        int r = rowBase + ty * TM + i;
        if (r >= N) continue;
        float dv = dinv[r];
#pragma unroll
        for (int j = 0; j < TN; j++) {
            C[(size_t)r * M + colBase + tx * TN + j] = acc[i][j] * dv;
        }
    }
}

// ---------------- propagate: out[i] = relu(dinv[i]*(p[i] + sum_in p[src]) + b) ----------------

template <int M>
__global__ void propagate_kernel(const float* __restrict__ p, const int* __restrict__ rowptr,
                                 const int* __restrict__ csr_src, const float* __restrict__ dinv,
                                 const float* __restrict__ bias, float* __restrict__ out) {
    constexpr int NPB = 256 / M;
    int node = blockIdx.x * NPB + threadIdx.y;
    if (node >= N_NODES) return;
    int f = threadIdx.x;

    float acc = p[(size_t)node * M + f];  // self-loop contribution (pre-dinv)
    int e = rowptr[node];
    int end = rowptr[node + 1];

    for (; e + 4 <= end; e += 4) {
        int s0 = csr_src[e + 0];
        int s1 = csr_src[e + 1];
        int s2 = csr_src[e + 2];
        int s3 = csr_src[e + 3];
        float v0 = p[(size_t)s0 * M + f];
        float v1 = p[(size_t)s1 * M + f];
        float v2 = p[(size_t)s2 * M + f];
        float v3 = p[(size_t)s3 * M + f];
        acc += (v0 + v1) + (v2 + v3);
    }
    for (; e < end; e++) acc += p[(size_t)csr_src[e] * M + f];

    out[(size_t)node * M + f] = fmaxf(fmaf(dinv[node], acc, bias[f]), 0.0f);
}

// ---------------- host-side drivers ----------------

static void run_gemm(const float* A, const float* B, const float* dinv, float* C,
                     int N, int K, int M) {
    if (M >= 128) {
        constexpr int BM = 128, BN = 128, BK = 16, TM = 8, TN = 8;
        dim3 grid(M / BN, (N + BM - 1) / BM);
        gemm_scaled_kernel<BM, BN, BK, TM, TN><<<grid, (BM / TM) * (BN / TN)>>>(A, B, dinv, C, N, K, M);
    } else if (M == 64) {
        constexpr int BM = 128, BN = 64, BK = 16, TM = 8, TN = 4;
        dim3 grid(M / BN, (N + BM - 1) / BM);
        gemm_scaled_kernel<BM, BN, BK, TM, TN><<<grid, (BM / TM) * (BN / TN)>>>(A, B, dinv, C, N, K, M);
    } else {  // M == 32
        constexpr int BM = 256, BN = 32, BK = 16, TM = 8, TN = 4;
        dim3 grid(M / BN, (N + BM - 1) / BM);
        gemm_scaled_kernel<BM, BN, BK, TM, TN><<<grid, (BM / TM) * (BN / TN)>>>(A, B, dinv, C, N, K, M);
    }
}

template <int M>
static void run_propagate(const float* p, const int* rowptr, const int* csr_src,
                          const float* dinv, const float* bias, float* out) {
    constexpr int NPB = 256 / M;
    dim3 block(M, NPB);
    dim3 grid((N_NODES + NPB - 1) / NPB);
    propagate_kernel<M><<<grid, block>>>(p, rowptr, csr_src, dinv, bias, out);
}

extern "C" void kernel_launch(void* const* d_in, const int* in_sizes, int n_in,
                              void* d_out, int out_size) {
    const float* x  = (const float*)d_in[0];
    const int*   ei = (const int*)d_in[1];
    const float* W1 = (const float*)d_in[2];
    const float* b1 = (const float*)d_in[3];
    const float* W2 = (const float*)d_in[4];
    const float* b2 = (const float*)d_in[5];
    const float* W3 = (const float*)d_in[6];
    const float* b3 = (const float*)d_in[7];
    const float* W4 = (const float*)d_in[8];
    const float* b4 = (const float*)d_in[9];

    const int E = in_sizes[1] / 2;

    float *p, *act, *dinv;
    int *ideg, *cursor, *rowptr, *csr_src, *partial;
    cudaGetSymbolAddress((void**)&p, g_p);
    cudaGetSymbolAddress((void**)&act, g_act);
    cudaGetSymbolAddress((void**)&dinv, g_dinv);
    cudaGetSymbolAddress((void**)&ideg, g_ideg);
    cudaGetSymbolAddress((void**)&cursor, g_cursor);
    cudaGetSymbolAddress((void**)&rowptr, g_rowptr);
    cudaGetSymbolAddress((void**)&csr_src, g_csr_src);
    cudaGetSymbolAddress((void**)&partial, g_partial);

    // --- prep: degree histogram, dinv, parallel scan, CSR fill ---
    init_counts_kernel<<<(N_NODES + 255) / 256, 256>>>(ideg, cursor);
    edge_count_kernel<<<(E + 255) / 256, 256>>>(ei, ideg, E);
    dinv_kernel<<<(N_NODES + 255) / 256, 256>>>(ideg, dinv);
    scan_reduce_kernel<<<NB_SCAN, 256>>>(ideg, partial);
    scan_partials_kernel<<<1, 256>>>(partial);
    scan_final_kernel<<<NB_SCAN, 256>>>(ideg, partial, rowptr);
    edge_fill_kernel<<<(E + 255) / 256, 256>>>(ei, rowptr, cursor, csr_src, E);

    // --- 4 GCN layers: p = dinv*(act@W); out = relu(dinv*(p_self + gather) + b) ---
    run_gemm(x,   W1, dinv, p, N_NODES, 128, 256);
    run_propagate<256>(p, rowptr, csr_src, dinv, b1, act);

    run_gemm(act, W2, dinv, p, N_NODES, 256, 128);
    run_propagate<128>(p, rowptr, csr_src, dinv, b2, act);

    run_gemm(act, W3, dinv, p, N_NODES, 128, 64);
    run_propagate<64>(p, rowptr, csr_src, dinv, b3, act);

    run_gemm(act, W4, dinv, p, N_NODES, 64, 32);
    run_propagate<32>(p, rowptr, csr_src, dinv, b4, (float*)d_out);
}